// round 3
// baseline (speedup 1.0000x reference)
#include <cuda_runtime.h>
#include <math.h>

// Problem constants
#define Bd   2
#define Nseq 2048
#define Dm   1024
#define Hh   16
#define HD   64
#define SCALE 0.125f   // 1/sqrt(64)

// Scratch (device globals; no allocation allowed)
__device__ float g_q[Bd*Hh*Nseq*HD];   // [B,H,N,64]
__device__ float g_k[Bd*Hh*Nseq*HD];
__device__ float g_v[Bd*Hh*Nseq*HD];
__device__ float g_att[Bd*Nseq*Dm];    // [B,N,D] attention output

// ---------------------------------------------------------------------------
// Tiled SGEMM: C[M,Nc] = A[M,K] @ W[K,Nc] + bias[Nc]
// Block tile 128x128, K-tile 16, 256 threads, 8x8 per thread via 2x2 of 4x4.
// MODE 0: A from param, plain write to C.
// MODE 1: A from param, scatter into g_q/g_k/g_v ([B,H,N,64]).
// MODE 2: A = g_att (device global), plain write to C.
// ---------------------------------------------------------------------------
template<int MODE>
__global__ void __launch_bounds__(256) sgemm_kernel(
    const float* __restrict__ Ain, const float* __restrict__ W,
    const float* __restrict__ bias, float* __restrict__ C,
    int M, int K, int Nc)
{
    __shared__ float As[16*128];   // transposed: [k][m]
    __shared__ float Ws[16*128];   // [k][n]

    const float* A = (MODE == 2) ? (const float*)g_att : Ain;

    const int tid = threadIdx.x;
    const int tx = tid & 15, ty = tid >> 4;
    const int m0 = blockIdx.y * 128;
    const int n0 = blockIdx.x * 128;

    float acc[2][2][4][4];
    #pragma unroll
    for (int a = 0; a < 2; a++)
        #pragma unroll
        for (int b = 0; b < 2; b++)
            #pragma unroll
            for (int i = 0; i < 4; i++)
                #pragma unroll
                for (int j = 0; j < 4; j++)
                    acc[a][b][i][j] = 0.f;

    for (int k0 = 0; k0 < K; k0 += 16) {
        // Load A tile (128x16) transposed and W tile (16x128)
        #pragma unroll
        for (int l = 0; l < 2; l++) {
            int s = tid + l * 256;            // 0..511 float4 slots
            int arow = s >> 2;                // 0..127
            int ac4  = (s & 3) * 4;           // 0,4,8,12
            float4 av = *(const float4*)&A[(size_t)(m0 + arow) * K + k0 + ac4];
            As[(ac4 + 0) * 128 + arow] = av.x;
            As[(ac4 + 1) * 128 + arow] = av.y;
            As[(ac4 + 2) * 128 + arow] = av.z;
            As[(ac4 + 3) * 128 + arow] = av.w;

            int wrow = s >> 5;                // 0..15
            int wc4  = (s & 31) * 4;          // 0..124
            *(float4*)&Ws[wrow * 128 + wc4] =
                *(const float4*)&W[(size_t)(k0 + wrow) * Nc + n0 + wc4];
        }
        __syncthreads();

        #pragma unroll 8
        for (int k = 0; k < 16; k++) {
            float4 a0 = *(float4*)&As[k * 128 + 4 * ty];
            float4 a1 = *(float4*)&As[k * 128 + 64 + 4 * ty];
            float4 b0 = *(float4*)&Ws[k * 128 + 4 * tx];
            float4 b1 = *(float4*)&Ws[k * 128 + 64 + 4 * tx];
            float ar[2][4] = {{a0.x, a0.y, a0.z, a0.w}, {a1.x, a1.y, a1.z, a1.w}};
            float br[2][4] = {{b0.x, b0.y, b0.z, b0.w}, {b1.x, b1.y, b1.z, b1.w}};
            #pragma unroll
            for (int ih = 0; ih < 2; ih++)
                #pragma unroll
                for (int jh = 0; jh < 2; jh++)
                    #pragma unroll
                    for (int i = 0; i < 4; i++)
                        #pragma unroll
                        for (int j = 0; j < 4; j++)
                            acc[ih][jh][i][j] += ar[ih][i] * br[jh][j];
        }
        __syncthreads();
    }

    // Epilogue
    #pragma unroll
    for (int ih = 0; ih < 2; ih++) {
        int rowb = m0 + ih * 64 + 4 * ty;
        #pragma unroll
        for (int jh = 0; jh < 2; jh++) {
            int col = n0 + jh * 64 + 4 * tx;
            float4 bz = *(const float4*)&bias[col];
            #pragma unroll
            for (int i = 0; i < 4; i++) {
                int row = rowb + i;
                float4 r;
                r.x = acc[ih][jh][i][0] + bz.x;
                r.y = acc[ih][jh][i][1] + bz.y;
                r.z = acc[ih][jh][i][2] + bz.z;
                r.w = acc[ih][jh][i][3] + bz.w;
                if (MODE != 1) {
                    *(float4*)&C[(size_t)row * Nc + col] = r;
                } else {
                    int bb = row >> 11;            // row / 2048
                    int nn = row & 2047;
                    int which = col >> 10;         // 0=q 1=k 2=v
                    int rem = col & 1023;
                    int hh = rem >> 6;
                    int dd = rem & 63;
                    float* dst = (which == 0) ? g_q : (which == 1) ? g_k : g_v;
                    *(float4*)&dst[(((size_t)(bb * Hh + hh)) * Nseq + nn) * HD + dd] = r;
                }
            }
        }
    }
}

// ---------------------------------------------------------------------------
// Flash attention: per (b,h,q-tile of 64). 256 threads (tx 0..15, ty 0..15),
// each computes a 4x4 sub-tile of the 64x64 S/P/O tiles.
// scores = q.k/8 + bias[k]; online softmax; O accumulated in registers.
// Static smem = 48KB exactly: Qt(16K) + Kt/Ps union(16K) + Vs(16K).
// ---------------------------------------------------------------------------
__global__ void __launch_bounds__(256) flash_kernel(const float* __restrict__ attn_bias)
{
    __shared__ float Qt[64 * 64];   // [d][r]
    __shared__ float Kt[64 * 64];   // [d][c] during S; reused as Ps[r][c] during PV
    __shared__ float Vs[64 * 64];   // [k][d]
    float* Ps = Kt;

    const int b = blockIdx.z, h = blockIdx.y;
    const int q0 = blockIdx.x * 64;
    const size_t head_off = (size_t)((b * Hh + h) * Nseq) * HD;
    const float* Qg = g_q + head_off;
    const float* Kg = g_k + head_off;
    const float* Vg = g_v + head_off;
    const float* biasg = attn_bias + b * Nseq;

    const int tid = threadIdx.x;
    const int tx = tid & 15, ty = tid >> 4;

    // Load Q tile transposed: consecutive threads -> consecutive rows,
    // smem column writes are conflict-free.
    for (int g = tid; g < 1024; g += 256) {
        int r  = g & 63;
        int c4 = (g >> 6) * 4;
        float4 qv = *(const float4*)&Qg[(size_t)(q0 + r) * HD + c4];
        Qt[(c4 + 0) * 64 + r] = qv.x;
        Qt[(c4 + 1) * 64 + r] = qv.y;
        Qt[(c4 + 2) * 64 + r] = qv.z;
        Qt[(c4 + 3) * 64 + r] = qv.w;
    }

    float m[4], l[4], o[4][4];
    #pragma unroll
    for (int i = 0; i < 4; i++) {
        m[i] = -1e30f; l[i] = 0.f;
        #pragma unroll
        for (int j = 0; j < 4; j++) o[i][j] = 0.f;
    }

    for (int k0 = 0; k0 < Nseq; k0 += 64) {
        __syncthreads();   // previous iteration done reading Ps(=Kt)/Vs; Qt write done
        // K tile transposed (conflict-free column writes), V tile straight
        for (int g = tid; g < 1024; g += 256) {
            int r  = g & 63;
            int c4 = (g >> 6) * 4;
            float4 kv = *(const float4*)&Kg[(size_t)(k0 + r) * HD + c4];
            Kt[(c4 + 0) * 64 + r] = kv.x;
            Kt[(c4 + 1) * 64 + r] = kv.y;
            Kt[(c4 + 2) * 64 + r] = kv.z;
            Kt[(c4 + 3) * 64 + r] = kv.w;
            *(float4*)&Vs[g * 4] = *(const float4*)&Vg[(size_t)k0 * HD + g * 4];
        }
        __syncthreads();

        // S = Q K^T  (64x64), 4x4 per thread
        float s[4][4];
        #pragma unroll
        for (int i = 0; i < 4; i++)
            #pragma unroll
            for (int j = 0; j < 4; j++) s[i][j] = 0.f;

        #pragma unroll 8
        for (int d = 0; d < 64; d++) {
            float4 qv = *(float4*)&Qt[d * 64 + 4 * ty];
            float4 kv = *(float4*)&Kt[d * 64 + 4 * tx];
            float qa[4] = {qv.x, qv.y, qv.z, qv.w};
            float ka[4] = {kv.x, kv.y, kv.z, kv.w};
            #pragma unroll
            for (int i = 0; i < 4; i++)
                #pragma unroll
                for (int j = 0; j < 4; j++)
                    s[i][j] += qa[i] * ka[j];
        }

        float4 bz = *(const float4*)&biasg[k0 + 4 * tx];
        float ba[4] = {bz.x, bz.y, bz.z, bz.w};

        // Online softmax per row (row spread over 16 tx threads)
        #pragma unroll
        for (int i = 0; i < 4; i++) {
            float sv[4];
            #pragma unroll
            for (int j = 0; j < 4; j++) sv[j] = s[i][j] * SCALE + ba[j];
            float tm = fmaxf(fmaxf(sv[0], sv[1]), fmaxf(sv[2], sv[3]));
            tm = fmaxf(tm, __shfl_xor_sync(0xffffffffu, tm, 1));
            tm = fmaxf(tm, __shfl_xor_sync(0xffffffffu, tm, 2));
            tm = fmaxf(tm, __shfl_xor_sync(0xffffffffu, tm, 4));
            tm = fmaxf(tm, __shfl_xor_sync(0xffffffffu, tm, 8));
            float mn = fmaxf(m[i], tm);
            float alpha = __expf(m[i] - mn);
            float ts = 0.f;
            #pragma unroll
            for (int j = 0; j < 4; j++) {
                float p = __expf(sv[j] - mn);
                s[i][j] = p;
                ts += p;
            }
            ts += __shfl_xor_sync(0xffffffffu, ts, 1);
            ts += __shfl_xor_sync(0xffffffffu, ts, 2);
            ts += __shfl_xor_sync(0xffffffffu, ts, 4);
            ts += __shfl_xor_sync(0xffffffffu, ts, 8);
            l[i] = l[i] * alpha + ts;
            m[i] = mn;
            #pragma unroll
            for (int j = 0; j < 4; j++) o[i][j] *= alpha;
        }

        __syncthreads();   // all warps done reading Kt before it becomes Ps

        // Write P row-major (conflict-free float4 stores)
        #pragma unroll
        for (int i = 0; i < 4; i++) {
            float4 pv;
            pv.x = s[i][0]; pv.y = s[i][1]; pv.z = s[i][2]; pv.w = s[i][3];
            *(float4*)&Ps[(4 * ty + i) * 64 + 4 * tx] = pv;
        }
        __syncthreads();

        // O += P V  (64x64 x 64x64)
        #pragma unroll 4
        for (int k = 0; k < 64; k++) {
            float4 vv = *(float4*)&Vs[k * 64 + 4 * tx];
            float va[4] = {vv.x, vv.y, vv.z, vv.w};
            float pa[4];
            #pragma unroll
            for (int i = 0; i < 4; i++) pa[i] = Ps[(4 * ty + i) * 64 + k];
            #pragma unroll
            for (int i = 0; i < 4; i++)
                #pragma unroll
                for (int j = 0; j < 4; j++)
                    o[i][j] += pa[i] * va[j];
        }
    }

    // Normalize and write to g_att [B,N,D]
    #pragma unroll
    for (int i = 0; i < 4; i++) {
        float inv = 1.0f / l[i];
        float4 r;
        r.x = o[i][0] * inv; r.y = o[i][1] * inv;
        r.z = o[i][2] * inv; r.w = o[i][3] * inv;
        *(float4*)&g_att[(size_t)(b * Nseq + q0 + 4 * ty + i) * Dm + h * HD + 4 * tx] = r;
    }
}

// ---------------------------------------------------------------------------
// Launch: three kernel launches, no other API calls (maximally capture-safe).
// ---------------------------------------------------------------------------
extern "C" void kernel_launch(void* const* d_in, const int* in_sizes, int n_in,
                              void* d_out, int out_size)
{
    const float* x         = (const float*)d_in[0];   // [2,2048,1024]
    const float* attn_bias = (const float*)d_in[1];   // [2,2048]
    const float* w_qkv     = (const float*)d_in[2];   // [1024,3072]
    const float* b_qkv     = (const float*)d_in[3];   // [3072]
    const float* w_proj    = (const float*)d_in[4];   // [1024,1024]
    const float* b_proj    = (const float*)d_in[5];   // [1024]
    float* out = (float*)d_out;

    // K1: QKV GEMM with head-split scatter
    {
        dim3 grid(3072 / 128, (Bd * Nseq) / 128);
        sgemm_kernel<1><<<grid, 256>>>(x, w_qkv, b_qkv, nullptr,
                                       Bd * Nseq, Dm, 3 * Dm);
    }

    // K2: flash attention (static 48KB smem)
    {
        dim3 grid(Nseq / 64, Hh, Bd);
        flash_kernel<<<grid, 256>>>(attn_bias);
    }

    // K3: projection GEMM reading A from g_att internally (MODE 2)
    {
        dim3 grid(Dm / 128, (Bd * Nseq) / 128);
        sgemm_kernel<2><<<grid, 256>>>(nullptr, w_proj, b_proj, out,
                                       Bd * Nseq, Dm, Dm);
    }
}

// round 5
// speedup vs baseline: 1.9420x; 1.9420x over previous
#include <cuda_runtime.h>
#include <cuda_bf16.h>
#include <stdint.h>

// Problem constants
#define Bd   2
#define Nseq 2048
#define Dm   1024
#define Hh   16
#define HD   64
#define SCALE 0.125f
#define Kdim 1024

// ---------------- device scratch (no allocations allowed) -------------------
__device__ __nv_bfloat16 g_xh[Bd*Nseq*Dm],  g_xl[Bd*Nseq*Dm];    // x split
__device__ __nv_bfloat16 g_wqh[3*Dm*Kdim],  g_wql[3*Dm*Kdim];    // w_qkv^T split [3072,1024]
__device__ __nv_bfloat16 g_wph[Dm*Kdim],    g_wpl[Dm*Kdim];      // w_proj^T split [1024,1024]
__device__ __nv_bfloat16 g_qh[Bd*Hh*Nseq*HD], g_ql[Bd*Hh*Nseq*HD]; // q*scale split [B,H,N,64]
__device__ __nv_bfloat16 g_kh[Bd*Hh*Nseq*HD], g_kl[Bd*Hh*Nseq*HD];
__device__ __nv_bfloat16 g_vh[Bd*Hh*Nseq*HD], g_vl[Bd*Hh*Nseq*HD];
__device__ __nv_bfloat16 g_ah[Bd*Nseq*Dm],  g_al[Bd*Nseq*Dm];    // attention out split

// ---------------- helpers ----------------------------------------------------
__device__ __forceinline__ uint32_t smem_u32(const void* p) {
    return (uint32_t)__cvta_generic_to_shared(p);
}
__device__ __forceinline__ void mma_bf16(float (&d)[4], const uint32_t (&a)[4],
                                         const uint32_t (&b)[2]) {
    asm volatile(
        "mma.sync.aligned.m16n8k16.row.col.f32.bf16.bf16.f32 "
        "{%0,%1,%2,%3}, {%4,%5,%6,%7}, {%8,%9}, {%0,%1,%2,%3};"
        : "+f"(d[0]), "+f"(d[1]), "+f"(d[2]), "+f"(d[3])
        : "r"(a[0]), "r"(a[1]), "r"(a[2]), "r"(a[3]), "r"(b[0]), "r"(b[1]));
}
__device__ __forceinline__ void ldsm4(uint32_t (&r)[4], uint32_t addr) {
    asm volatile("ldmatrix.sync.aligned.m8n8.x4.shared.b16 {%0,%1,%2,%3}, [%4];"
        : "=r"(r[0]), "=r"(r[1]), "=r"(r[2]), "=r"(r[3]) : "r"(addr));
}
__device__ __forceinline__ void ldsm4t(uint32_t (&r)[4], uint32_t addr) {
    asm volatile("ldmatrix.sync.aligned.m8n8.x4.trans.shared.b16 {%0,%1,%2,%3}, [%4];"
        : "=r"(r[0]), "=r"(r[1]), "=r"(r[2]), "=r"(r[3]) : "r"(addr));
}
// pack two floats into bf16x2 (lo in low 16 bits)
__device__ __forceinline__ uint32_t pack_bf16(float lo, float hi) {
    uint32_t r;
    asm("cvt.rn.bf16x2.f32 %0, %1, %2;" : "=r"(r) : "f"(hi), "f"(lo));
    return r;
}

// ---------------- split/transpose pre-passes --------------------------------
__global__ void __launch_bounds__(256) conv_x_kernel(const float* __restrict__ x) {
    int i4 = (blockIdx.x * 256 + threadIdx.x) * 4;
    if (i4 >= Bd * Nseq * Dm) return;
    float4 v = *(const float4*)&x[i4];
    __nv_bfloat16 hx = __float2bfloat16(v.x), hy = __float2bfloat16(v.y);
    __nv_bfloat16 hz = __float2bfloat16(v.z), hw = __float2bfloat16(v.w);
    *(__nv_bfloat162*)&g_xh[i4]     = __nv_bfloat162(hx, hy);
    *(__nv_bfloat162*)&g_xh[i4 + 2] = __nv_bfloat162(hz, hw);
    *(__nv_bfloat162*)&g_xl[i4]     = __nv_bfloat162(
        __float2bfloat16(v.x - __bfloat162float(hx)),
        __float2bfloat16(v.y - __bfloat162float(hy)));
    *(__nv_bfloat162*)&g_xl[i4 + 2] = __nv_bfloat162(
        __float2bfloat16(v.z - __bfloat162float(hz)),
        __float2bfloat16(v.w - __bfloat162float(hw)));
}

template<int WHICH>  // 0: qkv, 1: proj
__global__ void __launch_bounds__(256) convT_kernel(const float* __restrict__ w, int N) {
    __shared__ float t[32][33];
    int tx = threadIdx.x & 31, ty = threadIdx.x >> 5;   // 32 x 8
    int n0 = blockIdx.x * 32, k0 = blockIdx.y * 32;
    #pragma unroll
    for (int i = 0; i < 4; i++) {
        int k = k0 + ty + i * 8;
        t[ty + i * 8][tx] = w[(size_t)k * N + n0 + tx];
    }
    __syncthreads();
    __nv_bfloat16* dh = WHICH ? g_wph : g_wqh;
    __nv_bfloat16* dl = WHICH ? g_wpl : g_wql;
    #pragma unroll
    for (int i = 0; i < 4; i++) {
        int n = n0 + ty + i * 8;
        float v = t[tx][ty + i * 8];
        __nv_bfloat16 h = __float2bfloat16(v);
        dh[(size_t)n * Kdim + k0 + tx] = h;
        dl[(size_t)n * Kdim + k0 + tx] = __float2bfloat16(v - __bfloat162float(h));
    }
}

// ---------------- HMMA GEMM (bf16 x3 split) ----------------------------------
// 128x128 block tile, 8 warps (2m x 4n), warp tile 64x32, K-tile 32.
// MODE 1: A=g_xh/l, B=g_wqh/l, scatter to q/k/v (bf16 hi/lo, q pre-scaled).
// MODE 0: A=g_ah/l, B=g_wph/l, write fp32 C.
template<int MODE>
__global__ void __launch_bounds__(256) mma_gemm(const float* __restrict__ bias,
                                                float* __restrict__ C, int Nc) {
    __shared__ __nv_bfloat16 sAh[128 * 40], sAl[128 * 40];
    __shared__ __nv_bfloat16 sBh[128 * 40], sBl[128 * 40];

    const int tid = threadIdx.x, lane = tid & 31, wid = tid >> 5;
    const int m0 = blockIdx.y * 128, n0 = blockIdx.x * 128;
    const __nv_bfloat16* Ah = MODE ? g_xh  : g_ah;
    const __nv_bfloat16* Al = MODE ? g_xl  : g_al;
    const __nv_bfloat16* Bh = MODE ? g_wqh : g_wph;
    const __nv_bfloat16* Bl = MODE ? g_wql : g_wpl;
    const int wm = (wid >> 2) * 64, wn = (wid & 3) * 32;

    float acc[4][4][4] = {};

    const uint32_t aAh = smem_u32(sAh), aAl = smem_u32(sAl);
    const uint32_t aBh = smem_u32(sBh), aBl = smem_u32(sBl);
    const uint32_t lmr = (uint32_t)(lane & 15);
    const uint32_t lmc = (uint32_t)((lane >> 4) * 16);   // byte offset of k8 half

    for (int k0 = 0; k0 < Kdim; k0 += 32) {
        __syncthreads();
        #pragma unroll
        for (int l = 0; l < 2; l++) {
            int s = tid + l * 256;          // 512 uint4 slots: 128 rows x 4 chunks
            int r = s >> 2, c = s & 3;
            size_t ga = (size_t)(m0 + r) * Kdim + k0 + c * 8;
            size_t gb = (size_t)(n0 + r) * Kdim + k0 + c * 8;
            uint32_t so = (uint32_t)(r * 80 + c * 16);
            *(uint4*)((char*)sAh + so) = *(const uint4*)&Ah[ga];
            *(uint4*)((char*)sAl + so) = *(const uint4*)&Al[ga];
            *(uint4*)((char*)sBh + so) = *(const uint4*)&Bh[gb];
            *(uint4*)((char*)sBl + so) = *(const uint4*)&Bl[gb];
        }
        __syncthreads();

        #pragma unroll
        for (int kt = 0; kt < 2; kt++) {
            uint32_t ah[4][4], al[4][4], bh[4][2], bl[4][2];
            #pragma unroll
            for (int mi = 0; mi < 4; mi++) {
                uint32_t ro = (wm + mi * 16 + lmr) * 80 + kt * 32 + lmc;
                ldsm4(ah[mi], aAh + ro);
                ldsm4(al[mi], aAl + ro);
            }
            #pragma unroll
            for (int g = 0; g < 2; g++) {
                uint32_t ro = (wn + g * 16 + lmr) * 80 + kt * 32 + lmc;
                uint32_t t[4];
                ldsm4(t, aBh + ro);
                bh[2*g][0] = t[0]; bh[2*g][1] = t[2];
                bh[2*g+1][0] = t[1]; bh[2*g+1][1] = t[3];
                ldsm4(t, aBl + ro);
                bl[2*g][0] = t[0]; bl[2*g][1] = t[2];
                bl[2*g+1][0] = t[1]; bl[2*g+1][1] = t[3];
            }
            #pragma unroll
            for (int mi = 0; mi < 4; mi++)
                #pragma unroll
                for (int ni = 0; ni < 4; ni++) {
                    mma_bf16(acc[mi][ni], ah[mi], bh[ni]);
                    mma_bf16(acc[mi][ni], ah[mi], bl[ni]);
                    mma_bf16(acc[mi][ni], al[mi], bh[ni]);
                }
        }
    }

    // epilogue
    #pragma unroll
    for (int mi = 0; mi < 4; mi++) {
        int r0 = m0 + wm + mi * 16 + (lane >> 2);
        #pragma unroll
        for (int ni = 0; ni < 4; ni++) {
            int col = n0 + wn + ni * 8 + 2 * (lane & 3);
            float b0 = bias[col], b1 = bias[col + 1];
            #pragma unroll
            for (int rr = 0; rr < 2; rr++) {
                int row = r0 + rr * 8;
                float v0 = acc[mi][ni][rr * 2 + 0] + b0;
                float v1 = acc[mi][ni][rr * 2 + 1] + b1;
                if (MODE == 0) {
                    *(float2*)&C[(size_t)row * Nc + col] = make_float2(v0, v1);
                } else {
                    int bb = row >> 11, nn = row & 2047;
                    int which = col >> 10, rem = col & 1023;
                    int hh = rem >> 6, dd = rem & 63;
                    if (which == 0) { v0 *= SCALE; v1 *= SCALE; }
                    __nv_bfloat16 h0 = __float2bfloat16(v0), h1 = __float2bfloat16(v1);
                    __nv_bfloat16 l0 = __float2bfloat16(v0 - __bfloat162float(h0));
                    __nv_bfloat16 l1 = __float2bfloat16(v1 - __bfloat162float(h1));
                    size_t idx = (((size_t)(bb * Hh + hh)) * Nseq + nn) * HD + dd;
                    __nv_bfloat16* dh = (which == 0) ? g_qh : (which == 1) ? g_kh : g_vh;
                    __nv_bfloat16* dl = (which == 0) ? g_ql : (which == 1) ? g_kl : g_vl;
                    *(__nv_bfloat162*)&dh[idx] = __nv_bfloat162(h0, h1);
                    *(__nv_bfloat162*)&dl[idx] = __nv_bfloat162(l0, l1);
                }
            }
        }
    }
}

// ---------------- flash attention via HMMA -----------------------------------
// Block: 4 warps, Q-tile 64 (16 rows/warp, Q in registers), K-tile 64.
__global__ void __launch_bounds__(128) flash_mma(const float* __restrict__ attn_bias) {
    __shared__ __nv_bfloat16 sKh[64 * 72], sKl[64 * 72];
    __shared__ __nv_bfloat16 sVh[64 * 72], sVl[64 * 72];
    __shared__ float sBias[64];

    const int tid = threadIdx.x, lane = tid & 31, wid = tid >> 5;
    const int b = blockIdx.z, h = blockIdx.y, q0 = blockIdx.x * 64;
    const size_t hoff = (size_t)((b * Hh + h) * Nseq) * HD;
    const __nv_bfloat16 *Qhp = g_qh + hoff, *Qlp = g_ql + hoff;
    const __nv_bfloat16 *Khp = g_kh + hoff, *Klp = g_kl + hoff;
    const __nv_bfloat16 *Vhp = g_vh + hoff, *Vlp = g_vl + hoff;
    const float* biasg = attn_bias + b * Nseq;

    const uint32_t aKh = smem_u32(sKh), aKl = smem_u32(sKl);
    const uint32_t aVh = smem_u32(sVh), aVl = smem_u32(sVl);

    // stage Q (hi/lo) into the V buffers, load persistent A-fragments
    #pragma unroll
    for (int l = 0; l < 4; l++) {
        int s = tid + l * 128;              // 512 uint4: 64 rows x 8 chunks
        int r = s >> 3, c = s & 7;
        uint32_t so = (uint32_t)(r * 144 + c * 16);
        size_t g = (size_t)(q0 + r) * HD + c * 8;
        *(uint4*)((char*)sVh + so) = *(const uint4*)&Qhp[g];
        *(uint4*)((char*)sVl + so) = *(const uint4*)&Qlp[g];
    }
    __syncthreads();
    uint32_t qh[4][4], ql[4][4];
    {
        uint32_t rbase = (uint32_t)((wid * 16 + (lane & 15)) * 144 + (lane >> 4) * 16);
        #pragma unroll
        for (int kf = 0; kf < 4; kf++) {
            ldsm4(qh[kf], aVh + rbase + kf * 32);
            ldsm4(ql[kf], aVl + rbase + kf * 32);
        }
    }

    float O[8][4] = {};
    float mrow0 = -1e30f, mrow1 = -1e30f, lrow0 = 0.f, lrow1 = 0.f;

    for (int k0 = 0; k0 < Nseq; k0 += 64) {
        __syncthreads();   // everyone done with previous K/V (and the Q staging)
        #pragma unroll
        for (int l = 0; l < 4; l++) {
            int s = tid + l * 128;
            int r = s >> 3, c = s & 7;
            uint32_t so = (uint32_t)(r * 144 + c * 16);
            size_t g = (size_t)(k0 + r) * HD + c * 8;
            *(uint4*)((char*)sKh + so) = *(const uint4*)&Khp[g];
            *(uint4*)((char*)sKl + so) = *(const uint4*)&Klp[g];
            *(uint4*)((char*)sVh + so) = *(const uint4*)&Vhp[g];
            *(uint4*)((char*)sVl + so) = *(const uint4*)&Vlp[g];
        }
        if (tid < 16) *(float4*)&sBias[tid * 4] = *(const float4*)&biasg[k0 + tid * 4];
        __syncthreads();

        // ---- S = Q K^T ----
        float S[8][4] = {};
        #pragma unroll
        for (int kf = 0; kf < 4; kf++) {
            #pragma unroll
            for (int g = 0; g < 4; g++) {
                uint32_t ro = (uint32_t)((g * 16 + (lane & 15)) * 144 + kf * 32 + (lane >> 4) * 16);
                uint32_t t[4], bh0[2], bh1[2], bl0[2], bl1[2];
                ldsm4(t, aKh + ro);
                bh0[0] = t[0]; bh0[1] = t[2]; bh1[0] = t[1]; bh1[1] = t[3];
                ldsm4(t, aKl + ro);
                bl0[0] = t[0]; bl0[1] = t[2]; bl1[0] = t[1]; bl1[1] = t[3];
                mma_bf16(S[2*g],   qh[kf], bh0);
                mma_bf16(S[2*g],   qh[kf], bl0);
                mma_bf16(S[2*g],   ql[kf], bh0);
                mma_bf16(S[2*g+1], qh[kf], bh1);
                mma_bf16(S[2*g+1], qh[kf], bl1);
                mma_bf16(S[2*g+1], ql[kf], bh1);
            }
        }

        // ---- bias + online softmax ----
        float mx0 = mrow0, mx1 = mrow1;
        #pragma unroll
        for (int nt = 0; nt < 8; nt++) {
            float2 bb = *(float2*)&sBias[nt * 8 + 2 * (lane & 3)];
            S[nt][0] += bb.x; S[nt][1] += bb.y;
            S[nt][2] += bb.x; S[nt][3] += bb.y;
            mx0 = fmaxf(mx0, fmaxf(S[nt][0], S[nt][1]));
            mx1 = fmaxf(mx1, fmaxf(S[nt][2], S[nt][3]));
        }
        mx0 = fmaxf(mx0, __shfl_xor_sync(0xffffffffu, mx0, 1));
        mx0 = fmaxf(mx0, __shfl_xor_sync(0xffffffffu, mx0, 2));
        mx1 = fmaxf(mx1, __shfl_xor_sync(0xffffffffu, mx1, 1));
        mx1 = fmaxf(mx1, __shfl_xor_sync(0xffffffffu, mx1, 2));
        float alpha0 = __expf(mrow0 - mx0), alpha1 = __expf(mrow1 - mx1);
        mrow0 = mx0; mrow1 = mx1;
        float sum0 = 0.f, sum1 = 0.f;
        #pragma unroll
        for (int nt = 0; nt < 8; nt++) {
            S[nt][0] = __expf(S[nt][0] - mx0); S[nt][1] = __expf(S[nt][1] - mx0);
            S[nt][2] = __expf(S[nt][2] - mx1); S[nt][3] = __expf(S[nt][3] - mx1);
            sum0 += S[nt][0] + S[nt][1];
            sum1 += S[nt][2] + S[nt][3];
        }
        sum0 += __shfl_xor_sync(0xffffffffu, sum0, 1);
        sum0 += __shfl_xor_sync(0xffffffffu, sum0, 2);
        sum1 += __shfl_xor_sync(0xffffffffu, sum1, 1);
        sum1 += __shfl_xor_sync(0xffffffffu, sum1, 2);
        lrow0 = lrow0 * alpha0 + sum0;
        lrow1 = lrow1 * alpha1 + sum1;
        #pragma unroll
        for (int dt = 0; dt < 8; dt++) {
            O[dt][0] *= alpha0; O[dt][1] *= alpha0;
            O[dt][2] *= alpha1; O[dt][3] *= alpha1;
        }

        // ---- P -> A-fragments (exact hi/lo split, FA2 C->A identity) ----
        uint32_t pah[4][4], pal[4][4];
        #pragma unroll
        for (int kt = 0; kt < 4; kt++) {
            #pragma unroll
            for (int half = 0; half < 2; half++) {
                int nt = 2 * kt + half;
                float p0 = S[nt][0], p1 = S[nt][1], p2 = S[nt][2], p3 = S[nt][3];
                __nv_bfloat16 h0 = __float2bfloat16(p0), h1 = __float2bfloat16(p1);
                __nv_bfloat16 h2 = __float2bfloat16(p2), h3 = __float2bfloat16(p3);
                pah[kt][half * 2 + 0] = pack_bf16(__bfloat162float(h0), __bfloat162float(h1));
                pah[kt][half * 2 + 1] = pack_bf16(__bfloat162float(h2), __bfloat162float(h3));
                pal[kt][half * 2 + 0] = pack_bf16(p0 - __bfloat162float(h0), p1 - __bfloat162float(h1));
                pal[kt][half * 2 + 1] = pack_bf16(p2 - __bfloat162float(h2), p3 - __bfloat162float(h3));
            }
        }

        // ---- O += P V ----
        #pragma unroll
        for (int kt = 0; kt < 4; kt++) {
            #pragma unroll
            for (int g = 0; g < 4; g++) {
                uint32_t ro = (uint32_t)((kt * 16 + (lane & 7) + 8 * ((lane >> 3) & 1)) * 144
                                         + g * 32 + (lane >> 4) * 16);
                uint32_t t[4], vh0[2], vh1[2], vl0[2], vl1[2];
                ldsm4t(t, aVh + ro);
                vh0[0] = t[0]; vh0[1] = t[1]; vh1[0] = t[2]; vh1[1] = t[3];
                ldsm4t(t, aVl + ro);
                vl0[0] = t[0]; vl0[1] = t[1]; vl1[0] = t[2]; vl1[1] = t[3];
                mma_bf16(O[2*g],   pah[kt], vh0);
                mma_bf16(O[2*g],   pah[kt], vl0);
                mma_bf16(O[2*g],   pal[kt], vh0);
                mma_bf16(O[2*g+1], pah[kt], vh1);
                mma_bf16(O[2*g+1], pah[kt], vl1);
                mma_bf16(O[2*g+1], pal[kt], vh1);
            }
        }
    }

    // ---- epilogue: normalize, split to bf16 hi/lo for proj GEMM ----
    float inv0 = 1.f / lrow0, inv1 = 1.f / lrow1;
    int r0 = q0 + wid * 16 + (lane >> 2);
    #pragma unroll
    for (int dt = 0; dt < 8; dt++) {
        int col = h * HD + dt * 8 + 2 * (lane & 3);
        float v00 = O[dt][0] * inv0, v01 = O[dt][1] * inv0;
        float v10 = O[dt][2] * inv1, v11 = O[dt][3] * inv1;
        size_t i0 = (size_t)(b * Nseq + r0) * Dm + col;
        size_t i1 = (size_t)(b * Nseq + r0 + 8) * Dm + col;
        __nv_bfloat16 h00 = __float2bfloat16(v00), h01 = __float2bfloat16(v01);
        __nv_bfloat16 h10 = __float2bfloat16(v10), h11 = __float2bfloat16(v11);
        *(__nv_bfloat162*)&g_ah[i0] = __nv_bfloat162(h00, h01);
        *(__nv_bfloat162*)&g_ah[i1] = __nv_bfloat162(h10, h11);
        *(__nv_bfloat162*)&g_al[i0] = __nv_bfloat162(
            __float2bfloat16(v00 - __bfloat162float(h00)),
            __float2bfloat16(v01 - __bfloat162float(h01)));
        *(__nv_bfloat162*)&g_al[i1] = __nv_bfloat162(
            __float2bfloat16(v10 - __bfloat162float(h10)),
            __float2bfloat16(v11 - __bfloat162float(h11)));
    }
}

// ---------------- launch -----------------------------------------------------
extern "C" void kernel_launch(void* const* d_in, const int* in_sizes, int n_in,
                              void* d_out, int out_size)
{
    const float* x         = (const float*)d_in[0];
    const float* attn_bias = (const float*)d_in[1];
    const float* w_qkv     = (const float*)d_in[2];
    const float* b_qkv     = (const float*)d_in[3];
    const float* w_proj    = (const float*)d_in[4];
    const float* b_proj    = (const float*)d_in[5];
    float* out = (float*)d_out;

    conv_x_kernel<<<(Bd * Nseq * Dm) / (256 * 4), 256>>>(x);
    convT_kernel<0><<<dim3(3 * Dm / 32, Kdim / 32), 256>>>(w_qkv, 3 * Dm);
    convT_kernel<1><<<dim3(Dm / 32, Kdim / 32), 256>>>(w_proj, Dm);

    mma_gemm<1><<<dim3(3 * Dm / 128, (Bd * Nseq) / 128), 256>>>(b_qkv, nullptr, 3 * Dm);

    flash_mma<<<dim3(Nseq / 64, Hh, Bd), 128>>>(attn_bias);

    mma_gemm<0><<<dim3(Dm / 128, (Bd * Nseq) / 128), 256>>>(b_proj, out, Dm);
}

// round 6
// speedup vs baseline: 2.1397x; 1.1018x over previous
#include <cuda_runtime.h>
#include <cuda_bf16.h>
#include <stdint.h>

// Problem constants
#define Bd   2
#define Nseq 2048
#define Dm   1024
#define Hh   16
#define HD   64
#define SCALE 0.125f
#define Kdim 1024

// ---------------- device scratch (no allocations allowed) -------------------
__device__ __nv_bfloat16 g_xh[Bd*Nseq*Dm],  g_xl[Bd*Nseq*Dm];    // x split
__device__ __nv_bfloat16 g_wqh[3*Dm*Kdim],  g_wql[3*Dm*Kdim];    // w_qkv^T split [3072,1024]
__device__ __nv_bfloat16 g_wph[Dm*Kdim],    g_wpl[Dm*Kdim];      // w_proj^T split [1024,1024]
__device__ __nv_bfloat16 g_qh[Bd*Hh*Nseq*HD], g_ql[Bd*Hh*Nseq*HD]; // q*scale split [B,H,N,64]
__device__ __nv_bfloat16 g_kh[Bd*Hh*Nseq*HD], g_kl[Bd*Hh*Nseq*HD];
__device__ __nv_bfloat16 g_vh[Bd*Hh*Nseq*HD], g_vl[Bd*Hh*Nseq*HD];
__device__ __nv_bfloat16 g_ah[Bd*Nseq*Dm],  g_al[Bd*Nseq*Dm];    // attention out split

// ---------------- helpers ----------------------------------------------------
__device__ __forceinline__ uint32_t smem_u32(const void* p) {
    return (uint32_t)__cvta_generic_to_shared(p);
}
__device__ __forceinline__ void mma_bf16(float (&d)[4], const uint32_t (&a)[4],
                                         const uint32_t (&b)[2]) {
    asm volatile(
        "mma.sync.aligned.m16n8k16.row.col.f32.bf16.bf16.f32 "
        "{%0,%1,%2,%3}, {%4,%5,%6,%7}, {%8,%9}, {%0,%1,%2,%3};"
        : "+f"(d[0]), "+f"(d[1]), "+f"(d[2]), "+f"(d[3])
        : "r"(a[0]), "r"(a[1]), "r"(a[2]), "r"(a[3]), "r"(b[0]), "r"(b[1]));
}
__device__ __forceinline__ void ldsm4(uint32_t (&r)[4], uint32_t addr) {
    asm volatile("ldmatrix.sync.aligned.m8n8.x4.shared.b16 {%0,%1,%2,%3}, [%4];"
        : "=r"(r[0]), "=r"(r[1]), "=r"(r[2]), "=r"(r[3]) : "r"(addr));
}
__device__ __forceinline__ void ldsm4t(uint32_t (&r)[4], uint32_t addr) {
    asm volatile("ldmatrix.sync.aligned.m8n8.x4.trans.shared.b16 {%0,%1,%2,%3}, [%4];"
        : "=r"(r[0]), "=r"(r[1]), "=r"(r[2]), "=r"(r[3]) : "r"(addr));
}
__device__ __forceinline__ uint32_t pack_bf16(float lo, float hi) {
    uint32_t r;
    asm("cvt.rn.bf16x2.f32 %0, %1, %2;" : "=r"(r) : "f"(hi), "f"(lo));
    return r;
}

// ---------------- split/transpose pre-passes --------------------------------
__global__ void __launch_bounds__(256) conv_x_kernel(const float* __restrict__ x) {
    int i4 = (blockIdx.x * 256 + threadIdx.x) * 4;
    if (i4 >= Bd * Nseq * Dm) return;
    float4 v = *(const float4*)&x[i4];
    __nv_bfloat16 hx = __float2bfloat16(v.x), hy = __float2bfloat16(v.y);
    __nv_bfloat16 hz = __float2bfloat16(v.z), hw = __float2bfloat16(v.w);
    *(__nv_bfloat162*)&g_xh[i4]     = __nv_bfloat162(hx, hy);
    *(__nv_bfloat162*)&g_xh[i4 + 2] = __nv_bfloat162(hz, hw);
    *(__nv_bfloat162*)&g_xl[i4]     = __nv_bfloat162(
        __float2bfloat16(v.x - __bfloat162float(hx)),
        __float2bfloat16(v.y - __bfloat162float(hy)));
    *(__nv_bfloat162*)&g_xl[i4 + 2] = __nv_bfloat162(
        __float2bfloat16(v.z - __bfloat162float(hz)),
        __float2bfloat16(v.w - __bfloat162float(hw)));
}

template<int WHICH>  // 0: qkv, 1: proj
__global__ void __launch_bounds__(256) convT_kernel(const float* __restrict__ w, int N) {
    __shared__ float t[32][33];
    int tx = threadIdx.x & 31, ty = threadIdx.x >> 5;   // 32 x 8
    int n0 = blockIdx.x * 32, k0 = blockIdx.y * 32;
    #pragma unroll
    for (int i = 0; i < 4; i++) {
        int k = k0 + ty + i * 8;
        t[ty + i * 8][tx] = w[(size_t)k * N + n0 + tx];
    }
    __syncthreads();
    __nv_bfloat16* dh = WHICH ? g_wph : g_wqh;
    __nv_bfloat16* dl = WHICH ? g_wpl : g_wql;
    #pragma unroll
    for (int i = 0; i < 4; i++) {
        int n = n0 + ty + i * 8;
        float v = t[tx][ty + i * 8];
        __nv_bfloat16 h = __float2bfloat16(v);
        dh[(size_t)n * Kdim + k0 + tx] = h;
        dl[(size_t)n * Kdim + k0 + tx] = __float2bfloat16(v - __bfloat162float(h));
    }
}

// ---------------- HMMA GEMM (bf16 x3 split, register double-buffered) -------
// 128x128 block tile, 8 warps (2m x 4n), warp tile 64x32, K-tile 32.
template<int MODE>
__global__ void __launch_bounds__(256) mma_gemm(const float* __restrict__ bias,
                                                float* __restrict__ C, int Nc) {
    __shared__ __nv_bfloat16 sAh[128 * 40], sAl[128 * 40];
    __shared__ __nv_bfloat16 sBh[128 * 40], sBl[128 * 40];

    const int tid = threadIdx.x, lane = tid & 31, wid = tid >> 5;
    const int m0 = blockIdx.y * 128, n0 = blockIdx.x * 128;
    const __nv_bfloat16* Ah = MODE ? g_xh  : g_ah;
    const __nv_bfloat16* Al = MODE ? g_xl  : g_al;
    const __nv_bfloat16* Bh = MODE ? g_wqh : g_wph;
    const __nv_bfloat16* Bl = MODE ? g_wql : g_wpl;
    const int wm = (wid >> 2) * 64, wn = (wid & 3) * 32;

    float acc[4][4][4] = {};

    const uint32_t aAh = smem_u32(sAh), aAl = smem_u32(sAl);
    const uint32_t aBh = smem_u32(sBh), aBl = smem_u32(sBl);
    const uint32_t lmr = (uint32_t)(lane & 15);
    const uint32_t lmc = (uint32_t)((lane >> 4) * 16);

    // thread's 2 load slots: slot s = tid + l*256 -> row r = s>>2, chunk c = s&3
    const int r0s = tid >> 2, c0s = tid & 3;
    const int r1s = (tid + 256) >> 2, c1s = c0s;   // (s+256)&3 == s&3

    uint4 rAh[2], rAl[2], rBh[2], rBl[2];
    // preload first K-tile
    {
        size_t ga0 = (size_t)(m0 + r0s) * Kdim + c0s * 8;
        size_t ga1 = (size_t)(m0 + r1s) * Kdim + c1s * 8;
        size_t gb0 = (size_t)(n0 + r0s) * Kdim + c0s * 8;
        size_t gb1 = (size_t)(n0 + r1s) * Kdim + c1s * 8;
        rAh[0] = *(const uint4*)&Ah[ga0]; rAh[1] = *(const uint4*)&Ah[ga1];
        rAl[0] = *(const uint4*)&Al[ga0]; rAl[1] = *(const uint4*)&Al[ga1];
        rBh[0] = *(const uint4*)&Bh[gb0]; rBh[1] = *(const uint4*)&Bh[gb1];
        rBl[0] = *(const uint4*)&Bl[gb0]; rBl[1] = *(const uint4*)&Bl[gb1];
    }
    const uint32_t so0 = (uint32_t)(r0s * 80 + c0s * 16);
    const uint32_t so1 = (uint32_t)(r1s * 80 + c1s * 16);

    for (int k0 = 0; k0 < Kdim; k0 += 32) {
        __syncthreads();   // previous compute done reading smem
        *(uint4*)((char*)sAh + so0) = rAh[0]; *(uint4*)((char*)sAh + so1) = rAh[1];
        *(uint4*)((char*)sAl + so0) = rAl[0]; *(uint4*)((char*)sAl + so1) = rAl[1];
        *(uint4*)((char*)sBh + so0) = rBh[0]; *(uint4*)((char*)sBh + so1) = rBh[1];
        *(uint4*)((char*)sBl + so0) = rBl[0]; *(uint4*)((char*)sBl + so1) = rBl[1];
        __syncthreads();

        if (k0 + 32 < Kdim) {   // prefetch next tile into registers
            int kn = k0 + 32;
            size_t ga0 = (size_t)(m0 + r0s) * Kdim + kn + c0s * 8;
            size_t ga1 = (size_t)(m0 + r1s) * Kdim + kn + c1s * 8;
            size_t gb0 = (size_t)(n0 + r0s) * Kdim + kn + c0s * 8;
            size_t gb1 = (size_t)(n0 + r1s) * Kdim + kn + c1s * 8;
            rAh[0] = *(const uint4*)&Ah[ga0]; rAh[1] = *(const uint4*)&Ah[ga1];
            rAl[0] = *(const uint4*)&Al[ga0]; rAl[1] = *(const uint4*)&Al[ga1];
            rBh[0] = *(const uint4*)&Bh[gb0]; rBh[1] = *(const uint4*)&Bh[gb1];
            rBl[0] = *(const uint4*)&Bl[gb0]; rBl[1] = *(const uint4*)&Bl[gb1];
        }

        #pragma unroll
        for (int kt = 0; kt < 2; kt++) {
            uint32_t ah[4][4], al[4][4], bh[4][2], bl[4][2];
            #pragma unroll
            for (int mi = 0; mi < 4; mi++) {
                uint32_t ro = (wm + mi * 16 + lmr) * 80 + kt * 32 + lmc;
                ldsm4(ah[mi], aAh + ro);
                ldsm4(al[mi], aAl + ro);
            }
            #pragma unroll
            for (int g = 0; g < 2; g++) {
                uint32_t ro = (wn + g * 16 + lmr) * 80 + kt * 32 + lmc;
                uint32_t t[4];
                ldsm4(t, aBh + ro);
                bh[2*g][0] = t[0]; bh[2*g][1] = t[2];
                bh[2*g+1][0] = t[1]; bh[2*g+1][1] = t[3];
                ldsm4(t, aBl + ro);
                bl[2*g][0] = t[0]; bl[2*g][1] = t[2];
                bl[2*g+1][0] = t[1]; bl[2*g+1][1] = t[3];
            }
            #pragma unroll
            for (int mi = 0; mi < 4; mi++)
                #pragma unroll
                for (int ni = 0; ni < 4; ni++) {
                    mma_bf16(acc[mi][ni], ah[mi], bh[ni]);
                    mma_bf16(acc[mi][ni], ah[mi], bl[ni]);
                    mma_bf16(acc[mi][ni], al[mi], bh[ni]);
                }
        }
    }

    // epilogue
    #pragma unroll
    for (int mi = 0; mi < 4; mi++) {
        int r0 = m0 + wm + mi * 16 + (lane >> 2);
        #pragma unroll
        for (int ni = 0; ni < 4; ni++) {
            int col = n0 + wn + ni * 8 + 2 * (lane & 3);
            float b0 = bias[col], b1 = bias[col + 1];
            #pragma unroll
            for (int rr = 0; rr < 2; rr++) {
                int row = r0 + rr * 8;
                float v0 = acc[mi][ni][rr * 2 + 0] + b0;
                float v1 = acc[mi][ni][rr * 2 + 1] + b1;
                if (MODE == 0) {
                    *(float2*)&C[(size_t)row * Nc + col] = make_float2(v0, v1);
                } else {
                    int bb = row >> 11, nn = row & 2047;
                    int which = col >> 10, rem = col & 1023;
                    int hh = rem >> 6, dd = rem & 63;
                    if (which == 0) { v0 *= SCALE; v1 *= SCALE; }
                    __nv_bfloat16 h0 = __float2bfloat16(v0), h1 = __float2bfloat16(v1);
                    __nv_bfloat16 l0 = __float2bfloat16(v0 - __bfloat162float(h0));
                    __nv_bfloat16 l1 = __float2bfloat16(v1 - __bfloat162float(h1));
                    size_t idx = (((size_t)(bb * Hh + hh)) * Nseq + nn) * HD + dd;
                    __nv_bfloat16* dh = (which == 0) ? g_qh : (which == 1) ? g_kh : g_vh;
                    __nv_bfloat16* dl = (which == 0) ? g_ql : (which == 1) ? g_kl : g_vl;
                    *(__nv_bfloat162*)&dh[idx] = __nv_bfloat162(h0, h1);
                    *(__nv_bfloat162*)&dl[idx] = __nv_bfloat162(l0, l1);
                }
            }
        }
    }
}

// ---------------- flash attention via HMMA -----------------------------------
// Block: 8 warps, Q-tile 128 (16 rows/warp, Q in registers via direct gmem
// fragment loads), K-tile 64. Register double-buffered K/V loads.
__global__ void __launch_bounds__(256) flash_mma(const float* __restrict__ attn_bias) {
    __shared__ __nv_bfloat16 sKh[64 * 72], sKl[64 * 72];
    __shared__ __nv_bfloat16 sVh[64 * 72], sVl[64 * 72];
    __shared__ float sBias[64];

    const int tid = threadIdx.x, lane = tid & 31, wid = tid >> 5;
    const int b = blockIdx.z, h = blockIdx.y, q0 = blockIdx.x * 128;
    const size_t hoff = (size_t)((b * Hh + h) * Nseq) * HD;
    const __nv_bfloat16 *Qhp = g_qh + hoff, *Qlp = g_ql + hoff;
    const __nv_bfloat16 *Khp = g_kh + hoff, *Klp = g_kl + hoff;
    const __nv_bfloat16 *Vhp = g_vh + hoff, *Vlp = g_vl + hoff;
    const float* biasg = attn_bias + b * Nseq;

    const uint32_t aKh = smem_u32(sKh), aKl = smem_u32(sKl);
    const uint32_t aVh = smem_u32(sVh), aVl = smem_u32(sVl);

    // ---- load Q A-fragments directly from gmem ----
    // a-frag (m16n8k16): a0=(r,c), a1=(r+8,c), a2=(r,c+8), a3=(r+8,c+8),
    // r = lane>>2, c = 2*(lane&3); element pair is contiguous -> 32-bit load.
    uint32_t qh[4][4], ql[4][4];
    {
        int r = q0 + wid * 16 + (lane >> 2);
        int c = 2 * (lane & 3);
        #pragma unroll
        for (int kf = 0; kf < 4; kf++) {
            #pragma unroll
            for (int e = 0; e < 4; e++) {
                size_t g = (size_t)(r + (e & 1) * 8) * HD + kf * 16 + (e >> 1) * 8 + c;
                qh[kf][e] = *(const uint32_t*)&Qhp[g];
                ql[kf][e] = *(const uint32_t*)&Qlp[g];
            }
        }
    }

    // prefetch slots: slot s = tid + l*256 -> row r = s>>3, chunk c = s&7
    const int kr0 = tid >> 3, kc0 = tid & 7;
    const int kr1 = (tid + 256) >> 3, kc1 = kc0;
    const uint32_t fo0 = (uint32_t)(kr0 * 144 + kc0 * 16);
    const uint32_t fo1 = (uint32_t)(kr1 * 144 + kc1 * 16);

    uint4 rKh[2], rKl[2], rVh[2], rVl[2];
    float4 rBias;
    {
        size_t g0 = (size_t)kr0 * HD + kc0 * 8;
        size_t g1 = (size_t)kr1 * HD + kc1 * 8;
        rKh[0] = *(const uint4*)&Khp[g0]; rKh[1] = *(const uint4*)&Khp[g1];
        rKl[0] = *(const uint4*)&Klp[g0]; rKl[1] = *(const uint4*)&Klp[g1];
        rVh[0] = *(const uint4*)&Vhp[g0]; rVh[1] = *(const uint4*)&Vhp[g1];
        rVl[0] = *(const uint4*)&Vlp[g0]; rVl[1] = *(const uint4*)&Vlp[g1];
        if (tid < 16) rBias = *(const float4*)&biasg[tid * 4];
    }

    float O[8][4] = {};
    float mrow0 = -1e30f, mrow1 = -1e30f, lrow0 = 0.f, lrow1 = 0.f;

    for (int k0 = 0; k0 < Nseq; k0 += 64) {
        __syncthreads();   // previous PV reads done
        *(uint4*)((char*)sKh + fo0) = rKh[0]; *(uint4*)((char*)sKh + fo1) = rKh[1];
        *(uint4*)((char*)sKl + fo0) = rKl[0]; *(uint4*)((char*)sKl + fo1) = rKl[1];
        *(uint4*)((char*)sVh + fo0) = rVh[0]; *(uint4*)((char*)sVh + fo1) = rVh[1];
        *(uint4*)((char*)sVl + fo0) = rVl[0]; *(uint4*)((char*)sVl + fo1) = rVl[1];
        if (tid < 16) *(float4*)&sBias[tid * 4] = rBias;
        __syncthreads();

        if (k0 + 64 < Nseq) {
            int kn = k0 + 64;
            size_t g0 = (size_t)(kn + kr0) * HD + kc0 * 8;
            size_t g1 = (size_t)(kn + kr1) * HD + kc1 * 8;
            rKh[0] = *(const uint4*)&Khp[g0]; rKh[1] = *(const uint4*)&Khp[g1];
            rKl[0] = *(const uint4*)&Klp[g0]; rKl[1] = *(const uint4*)&Klp[g1];
            rVh[0] = *(const uint4*)&Vhp[g0]; rVh[1] = *(const uint4*)&Vhp[g1];
            rVl[0] = *(const uint4*)&Vlp[g0]; rVl[1] = *(const uint4*)&Vlp[g1];
            if (tid < 16) rBias = *(const float4*)&biasg[kn + tid * 4];
        }

        // ---- S = Q K^T ----
        float S[8][4] = {};
        #pragma unroll
        for (int kf = 0; kf < 4; kf++) {
            #pragma unroll
            for (int g = 0; g < 4; g++) {
                uint32_t ro = (uint32_t)((g * 16 + (lane & 15)) * 144 + kf * 32 + (lane >> 4) * 16);
                uint32_t t[4], bh0[2], bh1[2], bl0[2], bl1[2];
                ldsm4(t, aKh + ro);
                bh0[0] = t[0]; bh0[1] = t[2]; bh1[0] = t[1]; bh1[1] = t[3];
                ldsm4(t, aKl + ro);
                bl0[0] = t[0]; bl0[1] = t[2]; bl1[0] = t[1]; bl1[1] = t[3];
                mma_bf16(S[2*g],   qh[kf], bh0);
                mma_bf16(S[2*g],   qh[kf], bl0);
                mma_bf16(S[2*g],   ql[kf], bh0);
                mma_bf16(S[2*g+1], qh[kf], bh1);
                mma_bf16(S[2*g+1], qh[kf], bl1);
                mma_bf16(S[2*g+1], ql[kf], bh1);
            }
        }

        // ---- bias + online softmax ----
        float mx0 = mrow0, mx1 = mrow1;
        #pragma unroll
        for (int nt = 0; nt < 8; nt++) {
            float2 bb = *(float2*)&sBias[nt * 8 + 2 * (lane & 3)];
            S[nt][0] += bb.x; S[nt][1] += bb.y;
            S[nt][2] += bb.x; S[nt][3] += bb.y;
            mx0 = fmaxf(mx0, fmaxf(S[nt][0], S[nt][1]));
            mx1 = fmaxf(mx1, fmaxf(S[nt][2], S[nt][3]));
        }
        mx0 = fmaxf(mx0, __shfl_xor_sync(0xffffffffu, mx0, 1));
        mx0 = fmaxf(mx0, __shfl_xor_sync(0xffffffffu, mx0, 2));
        mx1 = fmaxf(mx1, __shfl_xor_sync(0xffffffffu, mx1, 1));
        mx1 = fmaxf(mx1, __shfl_xor_sync(0xffffffffu, mx1, 2));
        float alpha0 = __expf(mrow0 - mx0), alpha1 = __expf(mrow1 - mx1);
        mrow0 = mx0; mrow1 = mx1;
        float sum0 = 0.f, sum1 = 0.f;
        #pragma unroll
        for (int nt = 0; nt < 8; nt++) {
            S[nt][0] = __expf(S[nt][0] - mx0); S[nt][1] = __expf(S[nt][1] - mx0);
            S[nt][2] = __expf(S[nt][2] - mx1); S[nt][3] = __expf(S[nt][3] - mx1);
            sum0 += S[nt][0] + S[nt][1];
            sum1 += S[nt][2] + S[nt][3];
        }
        sum0 += __shfl_xor_sync(0xffffffffu, sum0, 1);
        sum0 += __shfl_xor_sync(0xffffffffu, sum0, 2);
        sum1 += __shfl_xor_sync(0xffffffffu, sum1, 1);
        sum1 += __shfl_xor_sync(0xffffffffu, sum1, 2);
        lrow0 = lrow0 * alpha0 + sum0;
        lrow1 = lrow1 * alpha1 + sum1;
        #pragma unroll
        for (int dt = 0; dt < 8; dt++) {
            O[dt][0] *= alpha0; O[dt][1] *= alpha0;
            O[dt][2] *= alpha1; O[dt][3] *= alpha1;
        }

        // ---- P -> A-fragments (hi/lo split) ----
        uint32_t pah[4][4], pal[4][4];
        #pragma unroll
        for (int kt = 0; kt < 4; kt++) {
            #pragma unroll
            for (int half = 0; half < 2; half++) {
                int nt = 2 * kt + half;
                float p0 = S[nt][0], p1 = S[nt][1], p2 = S[nt][2], p3 = S[nt][3];
                __nv_bfloat16 h0 = __float2bfloat16(p0), h1 = __float2bfloat16(p1);
                __nv_bfloat16 h2 = __float2bfloat16(p2), h3 = __float2bfloat16(p3);
                pah[kt][half * 2 + 0] = pack_bf16(__bfloat162float(h0), __bfloat162float(h1));
                pah[kt][half * 2 + 1] = pack_bf16(__bfloat162float(h2), __bfloat162float(h3));
                pal[kt][half * 2 + 0] = pack_bf16(p0 - __bfloat162float(h0), p1 - __bfloat162float(h1));
                pal[kt][half * 2 + 1] = pack_bf16(p2 - __bfloat162float(h2), p3 - __bfloat162float(h3));
            }
        }

        // ---- O += P V ----
        #pragma unroll
        for (int kt = 0; kt < 4; kt++) {
            #pragma unroll
            for (int g = 0; g < 4; g++) {
                uint32_t ro = (uint32_t)((kt * 16 + (lane & 7) + 8 * ((lane >> 3) & 1)) * 144
                                         + g * 32 + (lane >> 4) * 16);
                uint32_t t[4], vh0[2], vh1[2], vl0[2], vl1[2];
                ldsm4t(t, aVh + ro);
                vh0[0] = t[0]; vh0[1] = t[1]; vh1[0] = t[2]; vh1[1] = t[3];
                ldsm4t(t, aVl + ro);
                vl0[0] = t[0]; vl0[1] = t[1]; vl1[0] = t[2]; vl1[1] = t[3];
                mma_bf16(O[2*g],   pah[kt], vh0);
                mma_bf16(O[2*g],   pah[kt], vl0);
                mma_bf16(O[2*g],   pal[kt], vh0);
                mma_bf16(O[2*g+1], pah[kt], vh1);
                mma_bf16(O[2*g+1], pah[kt], vl1);
                mma_bf16(O[2*g+1], pal[kt], vh1);
            }
        }
    }

    // ---- epilogue ----
    float inv0 = 1.f / lrow0, inv1 = 1.f / lrow1;
    int r0 = q0 + wid * 16 + (lane >> 2);
    #pragma unroll
    for (int dt = 0; dt < 8; dt++) {
        int col = h * HD + dt * 8 + 2 * (lane & 3);
        float v00 = O[dt][0] * inv0, v01 = O[dt][1] * inv0;
        float v10 = O[dt][2] * inv1, v11 = O[dt][3] * inv1;
        size_t i0 = (size_t)(b * Nseq + r0) * Dm + col;
        size_t i1 = (size_t)(b * Nseq + r0 + 8) * Dm + col;
        __nv_bfloat16 h00 = __float2bfloat16(v00), h01 = __float2bfloat16(v01);
        __nv_bfloat16 h10 = __float2bfloat16(v10), h11 = __float2bfloat16(v11);
        *(__nv_bfloat162*)&g_ah[i0] = __nv_bfloat162(h00, h01);
        *(__nv_bfloat162*)&g_ah[i1] = __nv_bfloat162(h10, h11);
        *(__nv_bfloat162*)&g_al[i0] = __nv_bfloat162(
            __float2bfloat16(v00 - __bfloat162float(h00)),
            __float2bfloat16(v01 - __bfloat162float(h01)));
        *(__nv_bfloat162*)&g_al[i1] = __nv_bfloat162(
            __float2bfloat16(v10 - __bfloat162float(h10)),
            __float2bfloat16(v11 - __bfloat162float(h11)));
    }
}

// ---------------- launch -----------------------------------------------------
extern "C" void kernel_launch(void* const* d_in, const int* in_sizes, int n_in,
                              void* d_out, int out_size)
{
    const float* x         = (const float*)d_in[0];
    const float* attn_bias = (const float*)d_in[1];
    const float* w_qkv     = (const float*)d_in[2];
    const float* b_qkv     = (const float*)d_in[3];
    const float* w_proj    = (const float*)d_in[4];
    const float* b_proj    = (const float*)d_in[5];
    float* out = (float*)d_out;

    conv_x_kernel<<<(Bd * Nseq * Dm) / (256 * 4), 256>>>(x);
    convT_kernel<0><<<dim3(3 * Dm / 32, Kdim / 32), 256>>>(w_qkv, 3 * Dm);
    convT_kernel<1><<<dim3(Dm / 32, Kdim / 32), 256>>>(w_proj, Dm);

    mma_gemm<1><<<dim3(3 * Dm / 128, (Bd * Nseq) / 128), 256>>>(b_qkv, nullptr, 3 * Dm);

    flash_mma<<<dim3(Nseq / 128, Hh, Bd), 256>>>(attn_bias);

    mma_gemm<0><<<dim3(Dm / 128, (Bd * Nseq) / 128), 256>>>(b_proj, out, Dm);
}

// round 7
// speedup vs baseline: 2.1797x; 1.0187x over previous
#include <cuda_runtime.h>
#include <cuda_bf16.h>
#include <stdint.h>

// Problem constants
#define Bd   2
#define Nseq 2048
#define Dm   1024
#define Hh   16
#define HD   64
#define SCALE 0.125f
#define Kdim 1024

// ---------------- device scratch (no allocations allowed) -------------------
__device__ __nv_bfloat16 g_xh[Bd*Nseq*Dm],  g_xl[Bd*Nseq*Dm];    // x split
__device__ __nv_bfloat16 g_wqh[3*Dm*Kdim],  g_wql[3*Dm*Kdim];    // w_qkv^T split [3072,1024]
__device__ __nv_bfloat16 g_wph[Dm*Kdim],    g_wpl[Dm*Kdim];      // w_proj^T split [1024,1024]
__device__ __nv_bfloat16 g_qh[Bd*Hh*Nseq*HD], g_ql[Bd*Hh*Nseq*HD]; // q*scale split [B,H,N,64]
__device__ __nv_bfloat16 g_kh[Bd*Hh*Nseq*HD], g_kl[Bd*Hh*Nseq*HD];
__device__ __nv_bfloat16 g_vh[Bd*Hh*Nseq*HD], g_vl[Bd*Hh*Nseq*HD];
__device__ __nv_bfloat16 g_ah[Bd*Nseq*Dm],  g_al[Bd*Nseq*Dm];    // attention out split

// ---------------- helpers ----------------------------------------------------
__device__ __forceinline__ uint32_t smem_u32(const void* p) {
    return (uint32_t)__cvta_generic_to_shared(p);
}
__device__ __forceinline__ void mma_bf16(float (&d)[4], const uint32_t (&a)[4],
                                         const uint32_t (&b)[2]) {
    asm volatile(
        "mma.sync.aligned.m16n8k16.row.col.f32.bf16.bf16.f32 "
        "{%0,%1,%2,%3}, {%4,%5,%6,%7}, {%8,%9}, {%0,%1,%2,%3};"
        : "+f"(d[0]), "+f"(d[1]), "+f"(d[2]), "+f"(d[3])
        : "r"(a[0]), "r"(a[1]), "r"(a[2]), "r"(a[3]), "r"(b[0]), "r"(b[1]));
}
__device__ __forceinline__ void ldsm4(uint32_t (&r)[4], uint32_t addr) {
    asm volatile("ldmatrix.sync.aligned.m8n8.x4.shared.b16 {%0,%1,%2,%3}, [%4];"
        : "=r"(r[0]), "=r"(r[1]), "=r"(r[2]), "=r"(r[3]) : "r"(addr));
}
__device__ __forceinline__ void ldsm4t(uint32_t (&r)[4], uint32_t addr) {
    asm volatile("ldmatrix.sync.aligned.m8n8.x4.trans.shared.b16 {%0,%1,%2,%3}, [%4];"
        : "=r"(r[0]), "=r"(r[1]), "=r"(r[2]), "=r"(r[3]) : "r"(addr));
}
__device__ __forceinline__ uint32_t pack_bf16(float lo, float hi) {
    uint32_t r;
    asm("cvt.rn.bf16x2.f32 %0, %1, %2;" : "=r"(r) : "f"(hi), "f"(lo));
    return r;
}

// ---------------- split/transpose pre-passes --------------------------------
__global__ void __launch_bounds__(256) conv_x_kernel(const float* __restrict__ x) {
    int i4 = (blockIdx.x * 256 + threadIdx.x) * 4;
    if (i4 >= Bd * Nseq * Dm) return;
    float4 v = *(const float4*)&x[i4];
    __nv_bfloat16 hx = __float2bfloat16(v.x), hy = __float2bfloat16(v.y);
    __nv_bfloat16 hz = __float2bfloat16(v.z), hw = __float2bfloat16(v.w);
    *(__nv_bfloat162*)&g_xh[i4]     = __nv_bfloat162(hx, hy);
    *(__nv_bfloat162*)&g_xh[i4 + 2] = __nv_bfloat162(hz, hw);
    *(__nv_bfloat162*)&g_xl[i4]     = __nv_bfloat162(
        __float2bfloat16(v.x - __bfloat162float(hx)),
        __float2bfloat16(v.y - __bfloat162float(hy)));
    *(__nv_bfloat162*)&g_xl[i4 + 2] = __nv_bfloat162(
        __float2bfloat16(v.z - __bfloat162float(hz)),
        __float2bfloat16(v.w - __bfloat162float(hw)));
}

template<int WHICH>  // 0: qkv, 1: proj
__global__ void __launch_bounds__(256) convT_kernel(const float* __restrict__ w, int N) {
    __shared__ float t[32][33];
    int tx = threadIdx.x & 31, ty = threadIdx.x >> 5;   // 32 x 8
    int n0 = blockIdx.x * 32, k0 = blockIdx.y * 32;
    #pragma unroll
    for (int i = 0; i < 4; i++) {
        int k = k0 + ty + i * 8;
        t[ty + i * 8][tx] = w[(size_t)k * N + n0 + tx];
    }
    __syncthreads();
    __nv_bfloat16* dh = WHICH ? g_wph : g_wqh;
    __nv_bfloat16* dl = WHICH ? g_wpl : g_wql;
    #pragma unroll
    for (int i = 0; i < 4; i++) {
        int n = n0 + ty + i * 8;
        float v = t[tx][ty + i * 8];
        __nv_bfloat16 h = __float2bfloat16(v);
        dh[(size_t)n * Kdim + k0 + tx] = h;
        dl[(size_t)n * Kdim + k0 + tx] = __float2bfloat16(v - __bfloat162float(h));
    }
}

// ---------------- HMMA GEMM (bf16 x3 split, reg double-buffered, 2 CTA/SM) --
// 128(M)x64(N) block tile, 128 threads = 4 warps (2m x 2n), warp tile 64x32,
// K-tile 32.
template<int MODE>
__global__ void __launch_bounds__(128, 2) mma_gemm(const float* __restrict__ bias,
                                                   float* __restrict__ C, int Nc) {
    __shared__ __nv_bfloat16 sAh[128 * 40], sAl[128 * 40];
    __shared__ __nv_bfloat16 sBh[64 * 40],  sBl[64 * 40];

    const int tid = threadIdx.x, lane = tid & 31, wid = tid >> 5;
    const int m0 = blockIdx.y * 128, n0 = blockIdx.x * 64;
    const __nv_bfloat16* Ah = MODE ? g_xh  : g_ah;
    const __nv_bfloat16* Al = MODE ? g_xl  : g_al;
    const __nv_bfloat16* Bh = MODE ? g_wqh : g_wph;
    const __nv_bfloat16* Bl = MODE ? g_wql : g_wpl;
    const int wm = (wid >> 1) * 64, wn = (wid & 1) * 32;

    float acc[4][4][4] = {};

    const uint32_t aAh = smem_u32(sAh), aAl = smem_u32(sAl);
    const uint32_t aBh = smem_u32(sBh), aBl = smem_u32(sBl);
    const uint32_t lmr = (uint32_t)(lane & 15);
    const uint32_t lmc = (uint32_t)((lane >> 4) * 16);

    // load slots: base row rs = tid>>2, chunk cs = tid&3 (16B chunks of 64B row)
    const int rs = tid >> 2, cs = tid & 3;

    uint4 rAh[4], rAl[4], rBh[2], rBl[2];
    #pragma unroll
    for (int l = 0; l < 4; l++) {
        size_t ga = (size_t)(m0 + rs + l * 32) * Kdim + cs * 8;
        rAh[l] = *(const uint4*)&Ah[ga];
        rAl[l] = *(const uint4*)&Al[ga];
    }
    #pragma unroll
    for (int l = 0; l < 2; l++) {
        size_t gb = (size_t)(n0 + rs + l * 32) * Kdim + cs * 8;
        rBh[l] = *(const uint4*)&Bh[gb];
        rBl[l] = *(const uint4*)&Bl[gb];
    }
    const uint32_t soA = (uint32_t)(rs * 80 + cs * 16);

    for (int k0 = 0; k0 < Kdim; k0 += 32) {
        __syncthreads();   // previous compute done reading smem
        #pragma unroll
        for (int l = 0; l < 4; l++) {
            *(uint4*)((char*)sAh + soA + l * 32 * 80) = rAh[l];
            *(uint4*)((char*)sAl + soA + l * 32 * 80) = rAl[l];
        }
        #pragma unroll
        for (int l = 0; l < 2; l++) {
            *(uint4*)((char*)sBh + soA + l * 32 * 80) = rBh[l];
            *(uint4*)((char*)sBl + soA + l * 32 * 80) = rBl[l];
        }
        __syncthreads();

        if (k0 + 32 < Kdim) {   // prefetch next tile into registers
            int kn = k0 + 32;
            #pragma unroll
            for (int l = 0; l < 4; l++) {
                size_t ga = (size_t)(m0 + rs + l * 32) * Kdim + kn + cs * 8;
                rAh[l] = *(const uint4*)&Ah[ga];
                rAl[l] = *(const uint4*)&Al[ga];
            }
            #pragma unroll
            for (int l = 0; l < 2; l++) {
                size_t gb = (size_t)(n0 + rs + l * 32) * Kdim + kn + cs * 8;
                rBh[l] = *(const uint4*)&Bh[gb];
                rBl[l] = *(const uint4*)&Bl[gb];
            }
        }

        #pragma unroll
        for (int kt = 0; kt < 2; kt++) {
            uint32_t ah[4][4], al[4][4], bh[4][2], bl[4][2];
            #pragma unroll
            for (int mi = 0; mi < 4; mi++) {
                uint32_t ro = (wm + mi * 16 + lmr) * 80 + kt * 32 + lmc;
                ldsm4(ah[mi], aAh + ro);
                ldsm4(al[mi], aAl + ro);
            }
            #pragma unroll
            for (int g = 0; g < 2; g++) {
                uint32_t ro = (wn + g * 16 + lmr) * 80 + kt * 32 + lmc;
                uint32_t t[4];
                ldsm4(t, aBh + ro);
                bh[2*g][0] = t[0]; bh[2*g][1] = t[2];
                bh[2*g+1][0] = t[1]; bh[2*g+1][1] = t[3];
                ldsm4(t, aBl + ro);
                bl[2*g][0] = t[0]; bl[2*g][1] = t[2];
                bl[2*g+1][0] = t[1]; bl[2*g+1][1] = t[3];
            }
            #pragma unroll
            for (int mi = 0; mi < 4; mi++)
                #pragma unroll
                for (int ni = 0; ni < 4; ni++) {
                    mma_bf16(acc[mi][ni], ah[mi], bh[ni]);
                    mma_bf16(acc[mi][ni], ah[mi], bl[ni]);
                    mma_bf16(acc[mi][ni], al[mi], bh[ni]);
                }
        }
    }

    // epilogue
    #pragma unroll
    for (int mi = 0; mi < 4; mi++) {
        int r0 = m0 + wm + mi * 16 + (lane >> 2);
        #pragma unroll
        for (int ni = 0; ni < 4; ni++) {
            int col = n0 + wn + ni * 8 + 2 * (lane & 3);
            float b0 = bias[col], b1 = bias[col + 1];
            #pragma unroll
            for (int rr = 0; rr < 2; rr++) {
                int row = r0 + rr * 8;
                float v0 = acc[mi][ni][rr * 2 + 0] + b0;
                float v1 = acc[mi][ni][rr * 2 + 1] + b1;
                if (MODE == 0) {
                    *(float2*)&C[(size_t)row * Nc + col] = make_float2(v0, v1);
                } else {
                    int bb = row >> 11, nn = row & 2047;
                    int which = col >> 10, rem = col & 1023;
                    int hh = rem >> 6, dd = rem & 63;
                    if (which == 0) { v0 *= SCALE; v1 *= SCALE; }
                    __nv_bfloat16 h0 = __float2bfloat16(v0), h1 = __float2bfloat16(v1);
                    __nv_bfloat16 l0 = __float2bfloat16(v0 - __bfloat162float(h0));
                    __nv_bfloat16 l1 = __float2bfloat16(v1 - __bfloat162float(h1));
                    size_t idx = (((size_t)(bb * Hh + hh)) * Nseq + nn) * HD + dd;
                    __nv_bfloat16* dh = (which == 0) ? g_qh : (which == 1) ? g_kh : g_vh;
                    __nv_bfloat16* dl = (which == 0) ? g_ql : (which == 1) ? g_kl : g_vl;
                    *(__nv_bfloat162*)&dh[idx] = __nv_bfloat162(h0, h1);
                    *(__nv_bfloat162*)&dl[idx] = __nv_bfloat162(l0, l1);
                }
            }
        }
    }
}

// ---------------- flash attention via HMMA (unchanged from R6) ---------------
__global__ void __launch_bounds__(256) flash_mma(const float* __restrict__ attn_bias) {
    __shared__ __nv_bfloat16 sKh[64 * 72], sKl[64 * 72];
    __shared__ __nv_bfloat16 sVh[64 * 72], sVl[64 * 72];
    __shared__ float sBias[64];

    const int tid = threadIdx.x, lane = tid & 31, wid = tid >> 5;
    const int b = blockIdx.z, h = blockIdx.y, q0 = blockIdx.x * 128;
    const size_t hoff = (size_t)((b * Hh + h) * Nseq) * HD;
    const __nv_bfloat16 *Qhp = g_qh + hoff, *Qlp = g_ql + hoff;
    const __nv_bfloat16 *Khp = g_kh + hoff, *Klp = g_kl + hoff;
    const __nv_bfloat16 *Vhp = g_vh + hoff, *Vlp = g_vl + hoff;
    const float* biasg = attn_bias + b * Nseq;

    const uint32_t aKh = smem_u32(sKh), aKl = smem_u32(sKl);
    const uint32_t aVh = smem_u32(sVh), aVl = smem_u32(sVl);

    uint32_t qh[4][4], ql[4][4];
    {
        int r = q0 + wid * 16 + (lane >> 2);
        int c = 2 * (lane & 3);
        #pragma unroll
        for (int kf = 0; kf < 4; kf++) {
            #pragma unroll
            for (int e = 0; e < 4; e++) {
                size_t g = (size_t)(r + (e & 1) * 8) * HD + kf * 16 + (e >> 1) * 8 + c;
                qh[kf][e] = *(const uint32_t*)&Qhp[g];
                ql[kf][e] = *(const uint32_t*)&Qlp[g];
            }
        }
    }

    const int kr0 = tid >> 3, kc0 = tid & 7;
    const int kr1 = (tid + 256) >> 3, kc1 = kc0;
    const uint32_t fo0 = (uint32_t)(kr0 * 144 + kc0 * 16);
    const uint32_t fo1 = (uint32_t)(kr1 * 144 + kc1 * 16);

    uint4 rKh[2], rKl[2], rVh[2], rVl[2];
    float4 rBias;
    {
        size_t g0 = (size_t)kr0 * HD + kc0 * 8;
        size_t g1 = (size_t)kr1 * HD + kc1 * 8;
        rKh[0] = *(const uint4*)&Khp[g0]; rKh[1] = *(const uint4*)&Khp[g1];
        rKl[0] = *(const uint4*)&Klp[g0]; rKl[1] = *(const uint4*)&Klp[g1];
        rVh[0] = *(const uint4*)&Vhp[g0]; rVh[1] = *(const uint4*)&Vhp[g1];
        rVl[0] = *(const uint4*)&Vlp[g0]; rVl[1] = *(const uint4*)&Vlp[g1];
        if (tid < 16) rBias = *(const float4*)&biasg[tid * 4];
    }

    float O[8][4] = {};
    float mrow0 = -1e30f, mrow1 = -1e30f, lrow0 = 0.f, lrow1 = 0.f;

    for (int k0 = 0; k0 < Nseq; k0 += 64) {
        __syncthreads();
        *(uint4*)((char*)sKh + fo0) = rKh[0]; *(uint4*)((char*)sKh + fo1) = rKh[1];
        *(uint4*)((char*)sKl + fo0) = rKl[0]; *(uint4*)((char*)sKl + fo1) = rKl[1];
        *(uint4*)((char*)sVh + fo0) = rVh[0]; *(uint4*)((char*)sVh + fo1) = rVh[1];
        *(uint4*)((char*)sVl + fo0) = rVl[0]; *(uint4*)((char*)sVl + fo1) = rVl[1];
        if (tid < 16) *(float4*)&sBias[tid * 4] = rBias;
        __syncthreads();

        if (k0 + 64 < Nseq) {
            int kn = k0 + 64;
            size_t g0 = (size_t)(kn + kr0) * HD + kc0 * 8;
            size_t g1 = (size_t)(kn + kr1) * HD + kc1 * 8;
            rKh[0] = *(const uint4*)&Khp[g0]; rKh[1] = *(const uint4*)&Khp[g1];
            rKl[0] = *(const uint4*)&Klp[g0]; rKl[1] = *(const uint4*)&Klp[g1];
            rVh[0] = *(const uint4*)&Vhp[g0]; rVh[1] = *(const uint4*)&Vhp[g1];
            rVl[0] = *(const uint4*)&Vlp[g0]; rVl[1] = *(const uint4*)&Vlp[g1];
            if (tid < 16) rBias = *(const float4*)&biasg[kn + tid * 4];
        }

        float S[8][4] = {};
        #pragma unroll
        for (int kf = 0; kf < 4; kf++) {
            #pragma unroll
            for (int g = 0; g < 4; g++) {
                uint32_t ro = (uint32_t)((g * 16 + (lane & 15)) * 144 + kf * 32 + (lane >> 4) * 16);
                uint32_t t[4], bh0[2], bh1[2], bl0[2], bl1[2];
                ldsm4(t, aKh + ro);
                bh0[0] = t[0]; bh0[1] = t[2]; bh1[0] = t[1]; bh1[1] = t[3];
                ldsm4(t, aKl + ro);
                bl0[0] = t[0]; bl0[1] = t[2]; bl1[0] = t[1]; bl1[1] = t[3];
                mma_bf16(S[2*g],   qh[kf], bh0);
                mma_bf16(S[2*g],   qh[kf], bl0);
                mma_bf16(S[2*g],   ql[kf], bh0);
                mma_bf16(S[2*g+1], qh[kf], bh1);
                mma_bf16(S[2*g+1], qh[kf], bl1);
                mma_bf16(S[2*g+1], ql[kf], bh1);
            }
        }

        float mx0 = mrow0, mx1 = mrow1;
        #pragma unroll
        for (int nt = 0; nt < 8; nt++) {
            float2 bb = *(float2*)&sBias[nt * 8 + 2 * (lane & 3)];
            S[nt][0] += bb.x; S[nt][1] += bb.y;
            S[nt][2] += bb.x; S[nt][3] += bb.y;
            mx0 = fmaxf(mx0, fmaxf(S[nt][0], S[nt][1]));
            mx1 = fmaxf(mx1, fmaxf(S[nt][2], S[nt][3]));
        }
        mx0 = fmaxf(mx0, __shfl_xor_sync(0xffffffffu, mx0, 1));
        mx0 = fmaxf(mx0, __shfl_xor_sync(0xffffffffu, mx0, 2));
        mx1 = fmaxf(mx1, __shfl_xor_sync(0xffffffffu, mx1, 1));
        mx1 = fmaxf(mx1, __shfl_xor_sync(0xffffffffu, mx1, 2));
        float alpha0 = __expf(mrow0 - mx0), alpha1 = __expf(mrow1 - mx1);
        mrow0 = mx0; mrow1 = mx1;
        float sum0 = 0.f, sum1 = 0.f;
        #pragma unroll
        for (int nt = 0; nt < 8; nt++) {
            S[nt][0] = __expf(S[nt][0] - mx0); S[nt][1] = __expf(S[nt][1] - mx0);
            S[nt][2] = __expf(S[nt][2] - mx1); S[nt][3] = __expf(S[nt][3] - mx1);
            sum0 += S[nt][0] + S[nt][1];
            sum1 += S[nt][2] + S[nt][3];
        }
        sum0 += __shfl_xor_sync(0xffffffffu, sum0, 1);
        sum0 += __shfl_xor_sync(0xffffffffu, sum0, 2);
        sum1 += __shfl_xor_sync(0xffffffffu, sum1, 1);
        sum1 += __shfl_xor_sync(0xffffffffu, sum1, 2);
        lrow0 = lrow0 * alpha0 + sum0;
        lrow1 = lrow1 * alpha1 + sum1;
        #pragma unroll
        for (int dt = 0; dt < 8; dt++) {
            O[dt][0] *= alpha0; O[dt][1] *= alpha0;
            O[dt][2] *= alpha1; O[dt][3] *= alpha1;
        }

        uint32_t pah[4][4], pal[4][4];
        #pragma unroll
        for (int kt = 0; kt < 4; kt++) {
            #pragma unroll
            for (int half = 0; half < 2; half++) {
                int nt = 2 * kt + half;
                float p0 = S[nt][0], p1 = S[nt][1], p2 = S[nt][2], p3 = S[nt][3];
                __nv_bfloat16 h0 = __float2bfloat16(p0), h1 = __float2bfloat16(p1);
                __nv_bfloat16 h2 = __float2bfloat16(p2), h3 = __float2bfloat16(p3);
                pah[kt][half * 2 + 0] = pack_bf16(__bfloat162float(h0), __bfloat162float(h1));
                pah[kt][half * 2 + 1] = pack_bf16(__bfloat162float(h2), __bfloat162float(h3));
                pal[kt][half * 2 + 0] = pack_bf16(p0 - __bfloat162float(h0), p1 - __bfloat162float(h1));
                pal[kt][half * 2 + 1] = pack_bf16(p2 - __bfloat162float(h2), p3 - __bfloat162float(h3));
            }
        }

        #pragma unroll
        for (int kt = 0; kt < 4; kt++) {
            #pragma unroll
            for (int g = 0; g < 4; g++) {
                uint32_t ro = (uint32_t)((kt * 16 + (lane & 7) + 8 * ((lane >> 3) & 1)) * 144
                                         + g * 32 + (lane >> 4) * 16);
                uint32_t t[4], vh0[2], vh1[2], vl0[2], vl1[2];
                ldsm4t(t, aVh + ro);
                vh0[0] = t[0]; vh0[1] = t[1]; vh1[0] = t[2]; vh1[1] = t[3];
                ldsm4t(t, aVl + ro);
                vl0[0] = t[0]; vl0[1] = t[1]; vl1[0] = t[2]; vl1[1] = t[3];
                mma_bf16(O[2*g],   pah[kt], vh0);
                mma_bf16(O[2*g],   pah[kt], vl0);
                mma_bf16(O[2*g],   pal[kt], vh0);
                mma_bf16(O[2*g+1], pah[kt], vh1);
                mma_bf16(O[2*g+1], pah[kt], vl1);
                mma_bf16(O[2*g+1], pal[kt], vh1);
            }
        }
    }

    float inv0 = 1.f / lrow0, inv1 = 1.f / lrow1;
    int r0 = q0 + wid * 16 + (lane >> 2);
    #pragma unroll
    for (int dt = 0; dt < 8; dt++) {
        int col = h * HD + dt * 8 + 2 * (lane & 3);
        float v00 = O[dt][0] * inv0, v01 = O[dt][1] * inv0;
        float v10 = O[dt][2] * inv1, v11 = O[dt][3] * inv1;
        size_t i0 = (size_t)(b * Nseq + r0) * Dm + col;
        size_t i1 = (size_t)(b * Nseq + r0 + 8) * Dm + col;
        __nv_bfloat16 h00 = __float2bfloat16(v00), h01 = __float2bfloat16(v01);
        __nv_bfloat16 h10 = __float2bfloat16(v10), h11 = __float2bfloat16(v11);
        *(__nv_bfloat162*)&g_ah[i0] = __nv_bfloat162(h00, h01);
        *(__nv_bfloat162*)&g_ah[i1] = __nv_bfloat162(h10, h11);
        *(__nv_bfloat162*)&g_al[i0] = __nv_bfloat162(
            __float2bfloat16(v00 - __bfloat162float(h00)),
            __float2bfloat16(v01 - __bfloat162float(h01)));
        *(__nv_bfloat162*)&g_al[i1] = __nv_bfloat162(
            __float2bfloat16(v10 - __bfloat162float(h10)),
            __float2bfloat16(v11 - __bfloat162float(h11)));
    }
}

// ---------------- launch -----------------------------------------------------
extern "C" void kernel_launch(void* const* d_in, const int* in_sizes, int n_in,
                              void* d_out, int out_size)
{
    const float* x         = (const float*)d_in[0];
    const float* attn_bias = (const float*)d_in[1];
    const float* w_qkv     = (const float*)d_in[2];
    const float* b_qkv     = (const float*)d_in[3];
    const float* w_proj    = (const float*)d_in[4];
    const float* b_proj    = (const float*)d_in[5];
    float* out = (float*)d_out;

    conv_x_kernel<<<(Bd * Nseq * Dm) / (256 * 4), 256>>>(x);
    convT_kernel<0><<<dim3(3 * Dm / 32, Kdim / 32), 256>>>(w_qkv, 3 * Dm);
    convT_kernel<1><<<dim3(Dm / 32, Kdim / 32), 256>>>(w_proj, Dm);

    mma_gemm<1><<<dim3(3 * Dm / 64, (Bd * Nseq) / 128), 128>>>(b_qkv, nullptr, 3 * Dm);

    flash_mma<<<dim3(Nseq / 128, Hh, Bd), 256>>>(attn_bias);

    mma_gemm<0><<<dim3(Dm / 64, (Bd * Nseq) / 128), 128>>>(b_proj, out, Dm);
}